// round 2
// baseline (speedup 1.0000x reference)
#include <cuda_runtime.h>

#define BB 256
#define TT 256
#define CC 1024
#define LL 64
#define SS 129          // 2L+1
#define GW 68           // padded gather width: 64 labels + 1 blank
#define NEGV (-1e30f)
#define EPSF 1e-7f

// scratch buffers (no allocation allowed -> __device__ globals)
__device__ float g_buf[(size_t)BB * TT * GW];   // compact emit table g[b][t][j]
__device__ int   lab_buf[BB * LL];              // normalized int32 labels

// ---------------------------------------------------------------------------
// Kernel 0: normalize labels.  Detects on-device whether the label buffer is
// int64 (odd 32-bit words of the first 32 entries are all zero for values
// < 2^32) or int32, and writes canonical int32 labels.
// ---------------------------------------------------------------------------
__global__ void k_labels(const int* __restrict__ yt) {
    int i = blockIdx.x * blockDim.x + threadIdx.x;
    if (i >= BB * LL) return;
    bool is64 = true;
    #pragma unroll
    for (int k = 0; k < 32; ++k) is64 &= (yt[2 * k + 1] == 0);
    int v = is64 ? yt[2 * i] : yt[i];
    lab_buf[i] = min(max(v, 0), CC - 1);        // clamp: safety net
}

// ---------------------------------------------------------------------------
// Kernel 1: per (b,t) row — log_softmax(log(y+EPS)) = log(y+EPS) - log(sum(y+EPS)),
// so one plain sum over C suffices.  One warp per row; gather only the 65
// classes the CTC lattice can touch.
// ---------------------------------------------------------------------------
__global__ void k_reduce_gather(const float* __restrict__ yp) {
    int warp = (blockIdx.x * blockDim.x + threadIdx.x) >> 5;
    int lane = threadIdx.x & 31;
    if (warp >= BB * TT) return;
    int b = warp >> 8;                          // row-major (B,T,C)

    const float*  row  = yp + (size_t)warp * CC;
    const float4* row4 = (const float4*)row;

    float s = 0.f;
    #pragma unroll
    for (int k = 0; k < 8; ++k) {               // 8 coalesced float4 per lane
        float4 v = row4[lane + 32 * k];
        s += (v.x + v.y) + (v.z + v.w);
    }
    #pragma unroll
    for (int o = 16; o; o >>= 1) s += __shfl_xor_sync(0xffffffffu, s, o);

    float logZ = __logf(s + (float)CC * EPSF);  // log(sum(y+EPS))

    float* go = g_buf + (size_t)warp * GW;
    #pragma unroll
    for (int r = 0; r < 2; ++r) {
        int j   = lane + 32 * r;
        int lab = lab_buf[b * LL + j];
        go[j]   = __logf(row[lab] + EPSF) - logZ;    // L1 hit: row just read
    }
    if (lane == 0)
        go[64] = __logf(row[CC - 1] + EPSF) - logZ;  // blank
}

// ---------------------------------------------------------------------------
// Kernel 2: alpha recursion.  One warp per batch; each thread owns 5
// contiguous states; only 2 shuffles per time step; alphas live in registers.
// ---------------------------------------------------------------------------
__device__ __forceinline__ float stepf(float a1, float a2, float a3, float e) {
    float m = fmaxf(a1, fmaxf(a2, a3));
    float t = __expf(a1 - m) + __expf(a2 - m) + __expf(a3 - m);
    return m + __logf(t) + e;
}

__global__ void k_alpha(float* __restrict__ out) {
    int b    = (blockIdx.x * blockDim.x + threadIdx.x) >> 5;
    int lane = threadIdx.x & 31;
    if (b >= BB) return;

    int  eidx[5];
    bool valid[5], skip[5];
    #pragma unroll
    for (int i = 0; i < 5; ++i) {
        int s    = 5 * lane + i;
        valid[i] = (s < SS);
        bool odd = (s & 1);
        eidx[i]  = odd ? ((s - 1) >> 1) : 64;
        skip[i]  = false;
        if (valid[i] && odd && s >= 3) {        // pos>=2 and label state
            int j = (s - 1) >> 1;               // j >= 1 here
            skip[i] = (lab_buf[b * LL + j] != lab_buf[b * LL + j - 1]);
        }
    }

    const float* gb = g_buf + (size_t)b * TT * GW;

    // t = 0 init: only states 0,1 live
    float a[5];
    #pragma unroll
    for (int i = 0; i < 5; ++i) {
        int s = 5 * lane + i;
        a[i]  = (s < 2) ? gb[eidx[i]] : NEGV;
    }

    // prefetch emit for t = 1
    float e[5];
    {
        const float* gt = gb + GW;
        #pragma unroll
        for (int i = 0; i < 5; ++i) e[i] = valid[i] ? gt[eidx[i]] : NEGV;
    }

    for (int t = 1; t < TT; ++t) {
        float ec[5];
        #pragma unroll
        for (int i = 0; i < 5; ++i) ec[i] = e[i];
        if (t + 1 < TT) {                       // prefetch next emit row
            const float* gn = gb + (size_t)(t + 1) * GW;
            #pragma unroll
            for (int i = 0; i < 5; ++i) e[i] = valid[i] ? gn[eidx[i]] : NEGV;
        }

        float p4 = __shfl_up_sync(0xffffffffu, a[4], 1);   // state 5*lane-1
        float p3 = __shfl_up_sync(0xffffffffu, a[3], 1);   // state 5*lane-2
        if (lane == 0) { p4 = NEGV; p3 = NEGV; }

        float n0 = stepf(a[0], p4,   skip[0] ? p3   : NEGV, ec[0]);
        float n1 = stepf(a[1], a[0], skip[1] ? p4   : NEGV, ec[1]);
        float n2 = stepf(a[2], a[1], skip[2] ? a[0] : NEGV, ec[2]);
        float n3 = stepf(a[3], a[2], skip[3] ? a[1] : NEGV, ec[3]);
        float n4 = stepf(a[4], a[3], skip[4] ? a[2] : NEGV, ec[4]);
        a[0] = n0; a[1] = n1; a[2] = n2; a[3] = n3; a[4] = n4;
    }

    // states 127 (i=2) and 128 (i=3) live in lane 25
    if (lane == 25) {
        float x = a[2], y = a[3];
        float m = fmaxf(x, y);
        out[b] = -(m + __logf(__expf(x - m) + __expf(y - m)));
    }
}

// ---------------------------------------------------------------------------
extern "C" void kernel_launch(void* const* d_in, const int* in_sizes, int n_in,
                              void* d_out, int out_size) {
    // y_pred is by far the larger buffer; robust to metadata ordering.
    const float* yp;
    const int*   yt;
    if (in_sizes[0] > in_sizes[1]) {
        yp = (const float*)d_in[0];
        yt = (const int*)d_in[1];
    } else {
        yp = (const float*)d_in[1];
        yt = (const int*)d_in[0];
    }
    float* out = (float*)d_out;

    k_labels<<<(BB * LL + 255) / 256, 256>>>(yt);
    k_reduce_gather<<<(BB * TT) / 8, 256>>>(yp);   // one warp per (b,t) row
    k_alpha<<<BB / 4, 128>>>(out);                 // one warp per batch
}

// round 3
// speedup vs baseline: 1.0870x; 1.0870x over previous
#include <cuda_runtime.h>

#define BB 256
#define TT 256
#define CC 1024
#define LL 64
#define SS 129          // 2L+1
#define GW 68           // padded gather width: 64 labels + 1 blank
#define NEGV (-1e30f)
#define EPSF 1e-7f

// scratch (no allocation allowed -> __device__ global)
__device__ float g_buf[(size_t)BB * TT * GW];   // compact emit table g[b][t][j]

// int64-vs-int32 label dtype detection, one load + ballot per warp.
// int64 labels < 2^32 -> all odd 32-bit words zero; int32 random labels -> ~never.
__device__ __forceinline__ bool detect_i64(const int* yt, int lane) {
    return __all_sync(0xffffffffu, yt[2 * lane + 1] == 0);
}
__device__ __forceinline__ int load_lab(const int* yt, bool is64, int idx) {
    int v = is64 ? yt[2 * idx] : yt[idx];
    return min(max(v, 0), CC - 1);              // clamp: safety net
}

// ---------------------------------------------------------------------------
// Kernel 1: per (b,t) row.  log_softmax(log(y+EPS)) = log(y+EPS)-log(sum(y+EPS))
// -> one plain sum over C.  One warp per row; gather the 65 reachable classes.
// ---------------------------------------------------------------------------
__global__ void k_reduce_gather(const float* __restrict__ yp,
                                const int*   __restrict__ yt) {
    int warp = (blockIdx.x * blockDim.x + threadIdx.x) >> 5;
    int lane = threadIdx.x & 31;
    if (warp >= BB * TT) return;
    int b = warp >> 8;                          // row-major (B,T,C)

    bool is64 = detect_i64(yt, lane);

    const float*  row  = yp + (size_t)warp * CC;
    const float4* row4 = (const float4*)row;

    float s = 0.f;
    #pragma unroll
    for (int k = 0; k < 8; ++k) {               // 8 coalesced float4 per lane
        float4 v = row4[lane + 32 * k];
        s += (v.x + v.y) + (v.z + v.w);
    }
    #pragma unroll
    for (int o = 16; o; o >>= 1) s += __shfl_xor_sync(0xffffffffu, s, o);

    float logZ = __logf(s + (float)CC * EPSF);  // log(sum(y+EPS))

    float* go = g_buf + (size_t)warp * GW;
    #pragma unroll
    for (int r = 0; r < 2; ++r) {
        int j   = lane + 32 * r;
        int lab = load_lab(yt, is64, b * LL + j);
        go[j]   = __logf(row[lab] + EPSF) - logZ;    // L1 hit: row just read
    }
    if (lane == 0)
        go[64] = __logf(row[CC - 1] + EPSF) - logZ;  // blank
}

// ---------------------------------------------------------------------------
// Kernel 2: alpha recursion.  One warp per batch; each thread owns 5
// contiguous states; 2 shuffles per step; emit rows prefetched 3 steps deep.
// ---------------------------------------------------------------------------
__device__ __forceinline__ float stepf(float a1, float a2, float a3, float e) {
    float m = fmaxf(a1, fmaxf(a2, a3));
    float t = __expf(a1 - m) + __expf(a2 - m) + __expf(a3 - m);
    return m + __logf(t) + e;
}

__global__ void k_alpha(const int* __restrict__ yt, float* __restrict__ out) {
    int b    = (blockIdx.x * blockDim.x + threadIdx.x) >> 5;
    int lane = threadIdx.x & 31;
    if (b >= BB) return;

    bool is64 = detect_i64(yt, lane);

    int  eidx[5];
    bool valid[5], skip[5];
    #pragma unroll
    for (int i = 0; i < 5; ++i) {
        int s    = 5 * lane + i;
        valid[i] = (s < SS);
        bool odd = (s & 1);
        eidx[i]  = odd ? ((s - 1) >> 1) : 64;
        skip[i]  = false;
        if (valid[i] && odd && s >= 3) {        // pos>=2 and label state
            int j = (s - 1) >> 1;               // j >= 1 here
            skip[i] = (load_lab(yt, is64, b * LL + j) !=
                       load_lab(yt, is64, b * LL + j - 1));
        }
    }

    const float* gb = g_buf + (size_t)b * TT * GW;

    // t = 0 init: only states 0,1 live
    float a[5];
    #pragma unroll
    for (int i = 0; i < 5; ++i) {
        int s = 5 * lane + i;
        a[i]  = (s < 2) ? gb[eidx[i]] : NEGV;
    }

    // emit prefetch ring, depth 3 (t+1, t+2, t+3)
    float eb[3][5];
    #pragma unroll
    for (int d = 0; d < 3; ++d) {
        const float* gt = gb + (size_t)(1 + d) * GW;
        #pragma unroll
        for (int i = 0; i < 5; ++i) eb[d][i] = valid[i] ? gt[eidx[i]] : NEGV;
    }

    // (TT-1) = 255 steps = 85 chunks of 3; slots are compile-time constants
    for (int t = 1; t < TT; t += 3) {
        #pragma unroll
        for (int d = 0; d < 3; ++d) {
            int tc = t + d;
            float ec[5];
            #pragma unroll
            for (int i = 0; i < 5; ++i) ec[i] = eb[d][i];
            if (tc + 3 < TT) {                  // refill this slot from t+3 ahead
                const float* gn = gb + (size_t)(tc + 3) * GW;
                #pragma unroll
                for (int i = 0; i < 5; ++i) eb[d][i] = valid[i] ? gn[eidx[i]] : NEGV;
            }

            float p4 = __shfl_up_sync(0xffffffffu, a[4], 1);   // state 5*lane-1
            float p3 = __shfl_up_sync(0xffffffffu, a[3], 1);   // state 5*lane-2
            if (lane == 0) { p4 = NEGV; p3 = NEGV; }

            float n0 = stepf(a[0], p4,   skip[0] ? p3   : NEGV, ec[0]);
            float n1 = stepf(a[1], a[0], skip[1] ? p4   : NEGV, ec[1]);
            float n2 = stepf(a[2], a[1], skip[2] ? a[0] : NEGV, ec[2]);
            float n3 = stepf(a[3], a[2], skip[3] ? a[1] : NEGV, ec[3]);
            float n4 = stepf(a[4], a[3], skip[4] ? a[2] : NEGV, ec[4]);
            a[0] = n0; a[1] = n1; a[2] = n2; a[3] = n3; a[4] = n4;
        }
    }

    // states 127 (i=2) and 128 (i=3) live in lane 25
    if (lane == 25) {
        float x = a[2], y = a[3];
        float m = fmaxf(x, y);
        out[b] = -(m + __logf(__expf(x - m) + __expf(y - m)));
    }
}

// ---------------------------------------------------------------------------
extern "C" void kernel_launch(void* const* d_in, const int* in_sizes, int n_in,
                              void* d_out, int out_size) {
    // y_pred is by far the larger buffer; robust to metadata ordering.
    const float* yp;
    const int*   yt;
    if (in_sizes[0] > in_sizes[1]) {
        yp = (const float*)d_in[0];
        yt = (const int*)d_in[1];
    } else {
        yp = (const float*)d_in[1];
        yt = (const int*)d_in[0];
    }
    float* out = (float*)d_out;

    k_reduce_gather<<<(BB * TT) / 8, 256>>>(yp, yt);   // one warp per (b,t) row
    k_alpha<<<BB / 4, 128>>>(yt, out);                 // one warp per batch
}

// round 4
// speedup vs baseline: 1.9040x; 1.7516x over previous
#include <cuda_runtime.h>

#define BB 256
#define TT 256
#define CC 1024
#define LL 64
#define SS 129          // 2L+1
#define GW 68           // padded gather width: 64 labels + 1 blank
#define NEGV (-1e30f)
#define EPSF 1e-7f
#define LN2F 0.69314718055994530942f

// scratch (no allocation allowed -> __device__ global)
__device__ float g_buf[(size_t)BB * TT * GW];   // emit table, LOG2 domain

__device__ __forceinline__ float fexp2(float x) {
    float y; asm("ex2.approx.ftz.f32 %0, %1;" : "=f"(y) : "f"(x)); return y;
}
__device__ __forceinline__ float flog2(float x) {
    float y; asm("lg2.approx.ftz.f32 %0, %1;" : "=f"(y) : "f"(x)); return y;
}

// int64-vs-int32 label dtype detection, one load + ballot per warp.
__device__ __forceinline__ bool detect_i64(const int* yt, int lane) {
    return __all_sync(0xffffffffu, yt[2 * lane + 1] == 0);
}
__device__ __forceinline__ int load_lab(const int* yt, bool is64, int idx) {
    int v = is64 ? yt[2 * idx] : yt[idx];
    return min(max(v, 0), CC - 1);              // clamp: safety net
}

// ---------------------------------------------------------------------------
// Kernel 1: per (b,t) row.  log_softmax(log(y+EPS)) = log(y+EPS)-log(sum(y+EPS))
// -> one plain sum over C.  One warp per row; gather the 65 reachable classes.
// Emits in LOG2 domain.
// ---------------------------------------------------------------------------
__global__ void k_reduce_gather(const float* __restrict__ yp,
                                const int*   __restrict__ yt) {
    int warp = (blockIdx.x * blockDim.x + threadIdx.x) >> 5;
    int lane = threadIdx.x & 31;
    if (warp >= BB * TT) return;
    int b = warp >> 8;                          // row-major (B,T,C)

    bool is64 = detect_i64(yt, lane);

    const float*  row  = yp + (size_t)warp * CC;
    const float4* row4 = (const float4*)row;

    float s = 0.f;
    #pragma unroll
    for (int k = 0; k < 8; ++k) {               // 8 coalesced float4 per lane
        float4 v = row4[lane + 32 * k];
        s += (v.x + v.y) + (v.z + v.w);
    }
    #pragma unroll
    for (int o = 16; o; o >>= 1) s += __shfl_xor_sync(0xffffffffu, s, o);

    float l2Z = flog2(s + (float)CC * EPSF);    // log2(sum(y+EPS))

    float* go = g_buf + (size_t)warp * GW;
    #pragma unroll
    for (int r = 0; r < 2; ++r) {
        int j   = lane + 32 * r;
        int lab = load_lab(yt, is64, b * LL + j);
        go[j]   = flog2(row[lab] + EPSF) - l2Z;      // L1 hit: row just read
    }
    if (lane == 0)
        go[64] = flog2(row[CC - 1] + EPSF) - l2Z;    // blank
}

// ---------------------------------------------------------------------------
// Kernel 2: alpha recursion, LOG2 domain.  One warp per batch, 5 states per
// thread, 2 shuffles per step, emit prefetch ring depth 5.
// lse3 trick: one exp arg is always 0 -> t = 1 + 2^u + 2^v (2 MUFU + 1 log).
// ---------------------------------------------------------------------------
__device__ __forceinline__ float stepf(float a1, float a2, float a3, float e) {
    float mm = fmaxf(a1, a2);
    float mx = fmaxf(mm, a3);
    float u  = fminf(a1, a2) - mx;
    float v  = fminf(mm, a3) - mx;
    float t  = 1.0f + fexp2(u) + fexp2(v);
    return mx + flog2(t) + e;
}

__global__ void __launch_bounds__(128, 1)
k_alpha(const int* __restrict__ yt, float* __restrict__ out) {
    int b    = (blockIdx.x * blockDim.x + threadIdx.x) >> 5;
    int lane = threadIdx.x & 31;
    if (b >= BB) return;

    bool is64 = detect_i64(yt, lane);

    int  eidx[5];
    bool valid[5], skip[5];
    #pragma unroll
    for (int i = 0; i < 5; ++i) {
        int s    = 5 * lane + i;
        valid[i] = (s < SS);
        bool odd = (s & 1);
        eidx[i]  = odd ? ((s - 1) >> 1) : 64;
        skip[i]  = false;
        if (valid[i] && odd && s >= 3) {        // pos>=2 and label state
            int j = (s - 1) >> 1;               // j >= 1 here
            skip[i] = (load_lab(yt, is64, b * LL + j) !=
                       load_lab(yt, is64, b * LL + j - 1));
        }
    }

    const float* gb = g_buf + (size_t)b * TT * GW;

    // t = 0 init: only states 0,1 live
    float a[5];
    #pragma unroll
    for (int i = 0; i < 5; ++i) {
        int s = 5 * lane + i;
        a[i]  = (s < 2) ? gb[eidx[i]] : NEGV;
    }

    // emit prefetch ring, depth 5 (t+1 .. t+5)
    float eb[5][5];
    #pragma unroll
    for (int d = 0; d < 5; ++d) {
        const float* gt = gb + (size_t)(1 + d) * GW;
        #pragma unroll
        for (int i = 0; i < 5; ++i) eb[d][i] = valid[i] ? gt[eidx[i]] : NEGV;
    }

    // (TT-1) = 255 steps = 51 chunks of 5; ring slots are compile-time
    for (int t = 1; t < TT; t += 5) {
        #pragma unroll
        for (int d = 0; d < 5; ++d) {
            int tc = t + d;
            float ec[5];
            #pragma unroll
            for (int i = 0; i < 5; ++i) ec[i] = eb[d][i];
            if (tc + 5 < TT) {                  // refill this slot from 5 ahead
                const float* gn = gb + (size_t)(tc + 5) * GW;
                #pragma unroll
                for (int i = 0; i < 5; ++i) eb[d][i] = valid[i] ? gn[eidx[i]] : NEGV;
            }

            float p4 = __shfl_up_sync(0xffffffffu, a[4], 1);   // state 5*lane-1
            float p3 = __shfl_up_sync(0xffffffffu, a[3], 1);   // state 5*lane-2
            if (lane == 0) { p4 = NEGV; p3 = NEGV; }

            float n0 = stepf(a[0], p4,   skip[0] ? p3   : NEGV, ec[0]);
            float n1 = stepf(a[1], a[0], skip[1] ? p4   : NEGV, ec[1]);
            float n2 = stepf(a[2], a[1], skip[2] ? a[0] : NEGV, ec[2]);
            float n3 = stepf(a[3], a[2], skip[3] ? a[1] : NEGV, ec[3]);
            float n4 = stepf(a[4], a[3], skip[4] ? a[2] : NEGV, ec[4]);
            a[0] = n0; a[1] = n1; a[2] = n2; a[3] = n3; a[4] = n4;
        }
    }

    // states 127 (i=2) and 128 (i=3) live in lane 25; convert log2 -> ln
    if (lane == 25) {
        float x = a[2], y = a[3];
        float m = fmaxf(x, y);
        float r = m + flog2(1.0f + fexp2(fminf(x, y) - m));
        out[b] = -r * LN2F;
    }
}

// ---------------------------------------------------------------------------
extern "C" void kernel_launch(void* const* d_in, const int* in_sizes, int n_in,
                              void* d_out, int out_size) {
    // y_pred is by far the larger buffer; robust to metadata ordering.
    const float* yp;
    const int*   yt;
    if (in_sizes[0] > in_sizes[1]) {
        yp = (const float*)d_in[0];
        yt = (const int*)d_in[1];
    } else {
        yp = (const float*)d_in[1];
        yt = (const int*)d_in[0];
    }
    float* out = (float*)d_out;

    k_reduce_gather<<<(BB * TT) / 8, 256>>>(yp, yt);   // one warp per (b,t) row
    k_alpha<<<BB / 4, 128>>>(yt, out);                 // one warp per batch
}